// round 13
// baseline (speedup 1.0000x reference)
#include <cuda_runtime.h>
#include <cuda_fp16.h>
#include <cstdint>

// Problem constants
#define TT   512
#define BB   64
#define HID  1024
#define LAY  4
#define NWAVE (TT + LAY - 1)   // 515

// fp32 hidden ring: 2 MB, L2-resident
__device__ float g_ring[2][LAY][BB][HID];

// fp16 activation fragments, chunk-friendly layout: [slot][l][kc 0..63][bpair 0..31][tig] -> uint4
// uint4 = {ra:k0k1, rb:k0k1, ra:k8k9, rb:k8k9}; bpair p: ra=(p>>3)*16+(p&7), rb=ra+8
__device__ uint4 g_apack16[2][LAY][64][32][4];          // 1 MB

// fp16 x fragments: [t][kc][bpair][tig]
__device__ uint4 g_xpack16[TT][64][32][4];              // 67 MB

// fp16 weights, chunk-contiguous: [m=l*2+s][cb][ch 0..7][kl 0..7][gg][pl 0..15][tig] -> uint4
// per (m,cb,ch): 1536 uint4 = 24 KB contiguous
// uint4 = {ra:k0k1, ra:k8k9, rb:k0k1, rb:k8k9}
__device__ uint4 g_wpack16[8ull * 32 * 8 * 1536];       // 50.3 MB

// ---------- helpers ----------
__device__ __forceinline__ uint32_t f2h2(float x, float y) {
    __half2 h = __floats2half2_rn(x, y);
    return *reinterpret_cast<uint32_t*>(&h);
}

__device__ __forceinline__ void mma_fp16(float* c, const uint32_t* a, uint32_t b0, uint32_t b1) {
    asm volatile(
        "mma.sync.aligned.m16n8k16.row.col.f32.f16.f16.f32 "
        "{%0,%1,%2,%3},{%4,%5,%6,%7},{%8,%9},{%0,%1,%2,%3};"
        : "+f"(c[0]), "+f"(c[1]), "+f"(c[2]), "+f"(c[3])
        : "r"(a[0]), "r"(a[1]), "r"(a[2]), "r"(a[3]), "r"(b0), "r"(b1));
}

__device__ __forceinline__ uint32_t smem_u32(const void* p) {
    uint32_t a;
    asm("{ .reg .u64 t; cvta.to.shared.u64 t, %1; cvt.u32.u64 %0, t; }" : "=r"(a) : "l"(p));
    return a;
}
__device__ __forceinline__ void mbar_init(uint32_t m, uint32_t cnt) {
    asm volatile("mbarrier.init.shared.b64 [%0], %1;" :: "r"(m), "r"(cnt) : "memory");
}
__device__ __forceinline__ void mbar_arrive(uint32_t m) {
    asm volatile("mbarrier.arrive.shared.b64 _, [%0];" :: "r"(m) : "memory");
}
__device__ __forceinline__ void mbar_expect_tx(uint32_t m, uint32_t bytes) {
    asm volatile("mbarrier.arrive.expect_tx.shared.b64 _, [%0], %1;" :: "r"(m), "r"(bytes) : "memory");
}
__device__ __forceinline__ void mbar_wait(uint32_t m, uint32_t parity) {
    uint32_t done;
    asm volatile(
        "{\n\t.reg .pred p;\n\t"
        "mbarrier.try_wait.parity.acquire.cta.shared::cta.b64 p, [%1], %2;\n\t"
        "selp.b32 %0, 1, 0, p;\n\t}"
        : "=r"(done) : "r"(m), "r"(parity) : "memory");
    while (!done) {
        asm volatile(
            "{\n\t.reg .pred p;\n\t"
            "mbarrier.try_wait.parity.acquire.cta.shared::cta.b64 p, [%1], %2, 0x989680;\n\t"
            "selp.b32 %0, 1, 0, p;\n\t}"
            : "=r"(done) : "r"(m), "r"(parity) : "memory");
    }
}
__device__ __forceinline__ void bulk_cp(uint32_t dst, const void* src, uint32_t bytes, uint32_t m) {
    asm volatile("cp.async.bulk.shared::cluster.global.mbarrier::complete_tx::bytes "
                 "[%0], [%1], %2, [%3];"
                 :: "r"(dst), "l"(src), "r"(bytes), "r"(m) : "memory");
}

// ---------- weight packing (chunk-contiguous) ----------
__global__ void pack_weights16_kernel(const float* __restrict__ w_ih,
                                      const float* __restrict__ w_hh) {
    int64_t idx = (int64_t)blockIdx.x * blockDim.x + threadIdx.x;
    const int64_t total = 8ll * 32 * 8 * 1536;
    if (idx >= total) return;
    int tig = (int)(idx & 3);
    int pl  = (int)((idx >> 2) & 15);
    int64_t r = idx >> 6;
    int gg = (int)(r % 3);  r /= 3;
    int kl = (int)(r & 7);
    int ch = (int)((r >> 3) & 7);
    int cb = (int)((r >> 6) & 31);
    int m  = (int)(r >> 11);
    int l = m >> 1, s = m & 1;
    int kc = ch * 8 + kl;
    int ra = gg * HID + cb * 32 + (pl >> 3) * 16 + (pl & 7);
    const float* base = (s ? w_hh : w_ih) + (int64_t)l * 3072 * 1024;
    const float* sa = base + (int64_t)ra * 1024 + kc * 16 + 2 * tig;
    const float* sb = sa + 8 * 1024;
    uint4 q;
    q.x = f2h2(sa[0], sa[1]);
    q.y = f2h2(sa[8], sa[9]);
    q.z = f2h2(sb[0], sb[1]);
    q.w = f2h2(sb[8], sb[9]);
    g_wpack16[idx] = q;
}

// ---------- x packing ----------
__global__ void pack_x16_kernel(const float* __restrict__ x) {
    int64_t idx = (int64_t)blockIdx.x * blockDim.x + threadIdx.x;
    const int64_t total = (int64_t)TT * 64 * 32 * 4;
    if (idx >= total) return;
    int tig   = (int)(idx & 3);
    int bpair = (int)((idx >> 2) & 31);
    int kc    = (int)((idx >> 7) & 63);
    int t     = (int)(idx >> 13);
    int ba = (bpair >> 3) * 16 + (bpair & 7);
    const float* sa = x + ((int64_t)t * BB + ba) * HID + kc * 16 + 2 * tig;
    const float* sb = sa + 8 * HID;
    uint4 q;
    q.x = f2h2(sa[0], sa[1]);
    q.y = f2h2(sb[0], sb[1]);
    q.z = f2h2(sa[8], sa[9]);
    q.w = f2h2(sb[8], sb[9]);
    g_xpack16[t][kc][bpair][tig] = q;
}

// ---------- h0 init ----------
__global__ void init_h0_kernel(const float* __restrict__ h0) {
    int idx = blockIdx.x * blockDim.x + threadIdx.x;   // < L*64*32*4 = 32768
    int tig   = idx & 3;
    int bpair = (idx >> 2) & 31;
    int kc    = (idx >> 7) & 63;
    int l     = idx >> 13;
    int slot = (l + 1) & 1;
    int ba = (bpair >> 3) * 16 + (bpair & 7);
    const float* sa = h0 + ((int64_t)l * BB + ba) * HID + kc * 16 + 2 * tig;
    const float* sb = sa + 8 * HID;
    uint4 q;
    q.x = f2h2(sa[0], sa[1]);
    q.y = f2h2(sb[0], sb[1]);
    q.z = f2h2(sa[8], sa[9]);
    q.w = f2h2(sb[8], sb[9]);
    g_apack16[slot][l][kc][bpair][tig] = q;
    float* da = &g_ring[slot][l][ba][kc * 16 + 2 * tig];
    float* db = da + 8 * HID;
    da[0] = sa[0]; da[1] = sa[1]; da[8] = sa[8]; da[9] = sa[9];
    db[0] = sb[0]; db[1] = sb[1]; db[8] = sb[8]; db[9] = sb[9];
}

// ---------- smem layout ----------
#define NSTAGE 3
struct __align__(128) Smem {
    uint64_t full[NSTAGE];
    uint64_t empty[NSTAGE];
    uint4 bufA[NSTAGE][1024];   // 16 KB each
    uint4 bufB[NSTAGE][1536];   // 24 KB each
    float red[8][32][32];       // 32 KB
};

// ---------- wave kernel ----------
// grid = 128 (l = bx>>5, cb = bx&31), block = 512 (16 warps)
// warp = mstrip(0..3) x ksplit(0..1) x jhalf(0..1); ksplit splits kc within chunk.
// 16 chunks/wave (2 phases x 8); thread 0 streams A+B chunks via cp.async.bulk.
__global__ void __launch_bounds__(512, 1)
wave_kernel(const float* __restrict__ b_ih,
            const float* __restrict__ b_hh,
            int w) {
    const int l  = blockIdx.x >> 5;
    const int cb = blockIdx.x & 31;
    const int t  = w - l;
    if (t < 0 || t >= TT) return;

    extern __shared__ char smem_raw[];
    Smem* sm = reinterpret_cast<Smem*>(smem_raw);

    const int rs = (w + 1) & 1;
    const int ws = w & 1;

    const uint4* act0 = (l == 0) ? &g_xpack16[t][0][0][0]
                                 : &g_apack16[rs][l - 1][0][0][0];
    const uint4* act1 = &g_apack16[rs][l][0][0][0];
    const float* hprev = &g_ring[rs][l][0][0];
    float*       hout  = &g_ring[ws][l][0][0];

    const int lane = threadIdx.x & 31;
    const int warp = threadIdx.x >> 5;
    const int mstrip = warp & 3;
    const int ksplit = (warp >> 2) & 1;
    const int jhalf  = warp >> 3;
    const int gid = lane >> 2;
    const int tig = lane & 3;
    const int c0 = cb * 32;

    const int bpair = mstrip * 8 + gid;
    const int plw   = jhalf * 8 + gid;

    // barriers + addrs
    uint32_t full_a[NSTAGE], empty_a[NSTAGE], bufA_a[NSTAGE], bufB_a[NSTAGE];
#pragma unroll
    for (int i = 0; i < NSTAGE; ++i) {
        full_a[i]  = smem_u32(&sm->full[i]);
        empty_a[i] = smem_u32(&sm->empty[i]);
        bufA_a[i]  = smem_u32(&sm->bufA[i][0]);
        bufB_a[i]  = smem_u32(&sm->bufB[i][0]);
    }
    if (threadIdx.x == 0) {
#pragma unroll
        for (int i = 0; i < NSTAGE; ++i) {
            mbar_init(full_a[i], 1);
            mbar_init(empty_a[i], 512);
        }
    }
    __syncthreads();

    // weight chunk sources
    const uint4* wsrc0 = g_wpack16 + ((int64_t)((l * 2 + 0) * 32 + cb)) * (8 * 1536);
    const uint4* wsrc1 = g_wpack16 + ((int64_t)((l * 2 + 1) * 32 + cb)) * (8 * 1536);

    // producer prologue: issue chunks 0 and 1
    if (threadIdx.x == 0) {
#pragma unroll
        for (int cn = 0; cn < 2; ++cn) {
            mbar_expect_tx(full_a[cn], 40960u);
            bulk_cp(bufA_a[cn], act0 + cn * 1024, 16384u, full_a[cn]);
            bulk_cp(bufB_a[cn], wsrc0 + cn * 1536, 24576u, full_a[cn]);
        }
    }

    // ---- hoisted epilogue operands ----
    const int jtl   = ksplit;
    const int jbase = (jhalf * 2 + jtl) * 8 + tig * 2;
    const int cA = c0 + jbase;
    const float* bi = b_ih + l * 3 * HID;
    const float* bh = b_hh + l * 3 * HID;
    float bpr[2], bpz[2], bgn[2], bhn[2];
#pragma unroll
    for (int par = 0; par < 2; ++par) {
        const int c = cA + par;
        bpr[par] = bi[c] + bh[c];
        bpz[par] = bi[HID + c] + bh[HID + c];
        bgn[par] = bi[2 * HID + c];
        bhn[par] = bh[2 * HID + c];
    }
    float hpv[2][2];
#pragma unroll
    for (int half = 0; half < 2; ++half) {
        const int b = mstrip * 16 + gid + half * 8;
#pragma unroll
        for (int par = 0; par < 2; ++par)
            hpv[half][par] = hprev[(int64_t)b * HID + cA + par];
    }

    float acc[4][2][4];
#pragma unroll
    for (int g = 0; g < 4; ++g)
#pragma unroll
        for (int j = 0; j < 2; ++j)
#pragma unroll
            for (int r = 0; r < 4; ++r) acc[g][j][r] = 0.f;

    // ---- chunk loop: 16 chunks (phase = c>>3) ----
    for (int c = 0; c < 16; ++c) {
        const int st = c % NSTAGE;

        // producer: issue chunk c+2
        if (threadIdx.x == 0) {
            const int cn = c + 2;
            if (cn < 16) {
                const int sn = cn % NSTAGE;
                if (cn >= NSTAGE)
                    mbar_wait(empty_a[sn], (unsigned)((cn / NSTAGE) + 1) & 1);
                const int p  = cn >> 3;
                const int ci = cn & 7;
                const uint4* asrc = (p ? act1 : act0) + ci * 1024;
                const uint4* bsrc = (p ? wsrc1 : wsrc0) + ci * 1536;
                mbar_expect_tx(full_a[sn], 40960u);
                bulk_cp(bufA_a[sn], asrc, 16384u, full_a[sn]);
                bulk_cp(bufB_a[sn], bsrc, 24576u, full_a[sn]);
            }
        }

        mbar_wait(full_a[st], (unsigned)(c / NSTAGE) & 1);

        const uint4* bA = &sm->bufA[st][0];
        const uint4* bB = &sm->bufB[st][0];
        const int gt = (c >> 3) ? 3 : 2;

#pragma unroll
        for (int k4 = 0; k4 < 4; ++k4) {
            const int kl = ksplit * 4 + k4;
            uint4 qa = bA[(kl * 32 + bpair) * 4 + tig];
            uint32_t Ah[4] = {qa.x, qa.y, qa.z, qa.w};
            uint4 qb0 = bB[((kl * 3 + 0) * 16 + plw) * 4 + tig];
            uint4 qb1 = bB[((kl * 3 + 1) * 16 + plw) * 4 + tig];
            uint4 qb2 = bB[((kl * 3 + 2) * 16 + plw) * 4 + tig];
            mma_fp16(acc[0][0],  Ah, qb0.x, qb0.y);
            mma_fp16(acc[0][1],  Ah, qb0.z, qb0.w);
            mma_fp16(acc[1][0],  Ah, qb1.x, qb1.y);
            mma_fp16(acc[1][1],  Ah, qb1.z, qb1.w);
            mma_fp16(acc[gt][0], Ah, qb2.x, qb2.y);
            mma_fp16(acc[gt][1], Ah, qb2.z, qb2.w);
        }

        mbar_arrive(empty_a[st]);
    }

    // ---- cross-warp K reduction: each warp exports its "other" jtl ----
    {
        const int je = 1 - ksplit;
        float* dst = &sm->red[jhalf * 4 + mstrip][lane][je * 16];
#pragma unroll
        for (int g = 0; g < 4; ++g)
#pragma unroll
            for (int r = 0; r < 4; ++r) dst[g * 4 + r] = acc[g][je][r];
    }
    __syncthreads();

    // ---- gates for jtl = ksplit ----
    {
        const float* srcr = &sm->red[jhalf * 4 + mstrip][lane][jtl * 16];
#pragma unroll
        for (int g = 0; g < 4; ++g)
#pragma unroll
            for (int r = 0; r < 4; ++r) acc[g][jtl][r] += srcr[g * 4 + r];

        uint32_t frag[2];
#pragma unroll
        for (int half = 0; half < 2; ++half) {
            const int b = mstrip * 16 + gid + half * 8;
            float hnew[2];
#pragma unroll
            for (int par = 0; par < 2; ++par) {
                const int c = cA + par;
                const int ri = half * 2 + par;
                float pr  = acc[0][jtl][ri] + bpr[par];
                float pz  = acc[1][jtl][ri] + bpz[par];
                float gin = acc[2][jtl][ri] + bgn[par];
                float ghn = acc[3][jtl][ri] + bhn[par];
                float rr = 1.f / (1.f + __expf(-pr));
                float zz = 1.f / (1.f + __expf(-pz));
                float nn = tanhf(gin + rr * ghn);
                hnew[par] = (1.f - zz) * nn + zz * hpv[half][par];
                hout[(int64_t)b * HID + c] = hnew[par];
            }
            frag[half] = f2h2(hnew[0], hnew[1]);
        }
        // apack uint4 = {jtl0h0, jtl0h1, jtl1h0, jtl1h1}; this warp owns words [jtl*2, jtl*2+1]
        const int kc_out = cb * 2 + jhalf;
        uint2 q2; q2.x = frag[0]; q2.y = frag[1];
        char* base = (char*)(&g_apack16[ws][l][kc_out][bpair][tig]);
        *reinterpret_cast<uint2*>(base + jtl * 8) = q2;
    }
}

// ---------- output copy ----------
__global__ void copy_out_kernel(float* __restrict__ out) {
    int idx = blockIdx.x * blockDim.x + threadIdx.x;   // < L*B*H
    int l = idx >> 16;
    int rest = idx & 0xFFFF;
    int slot = (TT - 1 + l) & 1;
    out[idx] = (&g_ring[slot][l][0][0])[rest];
}

// ---------- launch ----------
extern "C" void kernel_launch(void* const* d_in, const int* in_sizes, int n_in,
                              void* d_out, int out_size) {
    const float* x    = (const float*)d_in[0];
    const float* h0   = (const float*)d_in[1];
    const float* w_ih = (const float*)d_in[2];
    const float* w_hh = (const float*)d_in[3];
    const float* b_ih = (const float*)d_in[4];
    const float* b_hh = (const float*)d_in[5];
    float* out = (float*)d_out;

    const int smem_bytes = (int)sizeof(Smem);
    static int configured = 0;
    if (!configured) {
        cudaFuncSetAttribute(wave_kernel,
                             cudaFuncAttributeMaxDynamicSharedMemorySize, smem_bytes);
        configured = 1;
    }

    {
        int64_t total = 8ll * 32 * 8 * 1536;
        pack_weights16_kernel<<<(int)((total + 255) / 256), 256>>>(w_ih, w_hh);
    }
    {
        int64_t total = (int64_t)TT * 64 * 32 * 4;
        pack_x16_kernel<<<(int)((total + 255) / 256), 256>>>(x);
    }
    init_h0_kernel<<<(LAY * 64 * 32 * 4) / 256, 256>>>(h0);

    for (int w = 0; w < NWAVE; ++w) {
        wave_kernel<<<128, 512, smem_bytes>>>(b_ih, b_hh, w);
    }

    copy_out_kernel<<<(LAY * BB * HID) / 256, 256>>>(out);
}

// round 14
// speedup vs baseline: 1.8833x; 1.8833x over previous
#include <cuda_runtime.h>
#include <cuda_fp16.h>
#include <cstdint>

// Problem constants
#define TT   512
#define BB   64
#define HID  1024
#define LAY  4
#define NWAVE (TT + LAY - 1)   // 515

// fp32 hidden ring (epilogue z*h term + final output): 2 MB, L2-resident
__device__ float g_ring[2][LAY][BB][HID];

// fp16 activation fragments: [slot][l][bpair 0..31][kc 0..63][tig 0..3] -> uint4
// bpair p: rows ra = (p>>3)*16 + (p&7), rb = ra+8
// uint4 = {ra:k0k1, rb:k0k1, ra:k8k9, rb:k8k9}
__device__ uint4 g_apack16[2][LAY][32][64][4];          // 1 MB

// fp16 x fragments: [t][bpair][kc][tig]
__device__ uint4 g_xpack16[TT][32][64][4];              // 16.8 MB

// fp16 weights: [m=l*2+s][kc][gg][p 0..511][tig] -> uint4
// uint4 = {ra:k0k1, ra:k8k9, rb:k0k1, rb:k8k9}
__device__ uint4 g_wpack16[8ull * 64 * 3 * 512 * 4];    // 50.3 MB

// ---------- helpers ----------
__device__ __forceinline__ uint32_t f2h2(float x, float y) {
    __half2 h = __floats2half2_rn(x, y);
    return *reinterpret_cast<uint32_t*>(&h);
}

__device__ __forceinline__ void mma_fp16(float* c, const uint32_t* a, uint32_t b0, uint32_t b1) {
    asm volatile(
        "mma.sync.aligned.m16n8k16.row.col.f32.f16.f16.f32 "
        "{%0,%1,%2,%3},{%4,%5,%6,%7},{%8,%9},{%0,%1,%2,%3};"
        : "+f"(c[0]), "+f"(c[1]), "+f"(c[2]), "+f"(c[3])
        : "r"(a[0]), "r"(a[1]), "r"(a[2]), "r"(a[3]), "r"(b0), "r"(b1));
}

// ---------- weight packing ----------
__global__ void pack_weights16_kernel(const float* __restrict__ w_ih,
                                      const float* __restrict__ w_hh) {
    int64_t idx = (int64_t)blockIdx.x * blockDim.x + threadIdx.x;
    const int64_t total = 8ll * 64 * 3 * 512 * 4;
    if (idx >= total) return;
    int tig = (int)(idx & 3);
    int64_t t2 = idx >> 2;
    int p  = (int)(t2 & 511);  t2 >>= 9;
    int gg = (int)(t2 % 3);    t2 /= 3;
    int kc = (int)(t2 & 63);
    int m  = (int)(t2 >> 6);
    int l = m >> 1, s = m & 1;
    int ra = gg * HID + (p >> 3) * 16 + (p & 7);
    const float* base = (s ? w_hh : w_ih) + (int64_t)l * 3072 * 1024;
    const float* sa = base + (int64_t)ra * 1024 + kc * 16 + 2 * tig;
    const float* sb = sa + 8 * 1024;
    uint4 q;
    q.x = f2h2(sa[0], sa[1]);
    q.y = f2h2(sa[8], sa[9]);
    q.z = f2h2(sb[0], sb[1]);
    q.w = f2h2(sb[8], sb[9]);
    g_wpack16[idx] = q;
}

// ---------- x packing ----------
__global__ void pack_x16_kernel(const float* __restrict__ x) {
    int64_t idx = (int64_t)blockIdx.x * blockDim.x + threadIdx.x;
    const int64_t total = (int64_t)TT * 32 * 64 * 4;
    if (idx >= total) return;
    int tig   = (int)(idx & 3);
    int kc    = (int)((idx >> 2) & 63);
    int bpair = (int)((idx >> 8) & 31);
    int t     = (int)(idx >> 13);
    int ba = (bpair >> 3) * 16 + (bpair & 7);
    const float* sa = x + ((int64_t)t * BB + ba) * HID + kc * 16 + 2 * tig;
    const float* sb = sa + 8 * HID;
    uint4 q;
    q.x = f2h2(sa[0], sa[1]);
    q.y = f2h2(sb[0], sb[1]);
    q.z = f2h2(sa[8], sa[9]);
    q.w = f2h2(sb[8], sb[9]);
    g_xpack16[t][bpair][kc][tig] = q;
}

// ---------- h0 init: fp32 ring + fp16 fragments ----------
__global__ void init_h0_kernel(const float* __restrict__ h0) {
    int idx = blockIdx.x * blockDim.x + threadIdx.x;   // < L*32*64*4 = 32768
    int tig   = idx & 3;
    int kc    = (idx >> 2) & 63;
    int bpair = (idx >> 8) & 31;
    int l     = idx >> 13;
    int slot = (l + 1) & 1;                            // read-slot of wave l
    int ba = (bpair >> 3) * 16 + (bpair & 7);
    const float* sa = h0 + ((int64_t)l * BB + ba) * HID + kc * 16 + 2 * tig;
    const float* sb = sa + 8 * HID;
    uint4 q;
    q.x = f2h2(sa[0], sa[1]);
    q.y = f2h2(sb[0], sb[1]);
    q.z = f2h2(sa[8], sa[9]);
    q.w = f2h2(sb[8], sb[9]);
    g_apack16[slot][l][bpair][kc][tig] = q;
    float* da = &g_ring[slot][l][ba][kc * 16 + 2 * tig];
    float* db = da + 8 * HID;
    da[0] = sa[0]; da[1] = sa[1]; da[8] = sa[8]; da[9] = sa[9];
    db[0] = sb[0]; db[1] = sb[1]; db[8] = sb[8]; db[9] = sb[9];
}

// ---------- wave kernel ----------
// grid = 128 (l = bx>>5, cb = bx&31), block = 512 (16 warps)
// warp = mstrip(0..3) x ksplit(0..1) x jhalf(0..1)
// k-loop = exact R6 champion body; epilogue split + hoisted operands.
__global__ void __launch_bounds__(512, 1)
wave_kernel(const float* __restrict__ b_ih,
            const float* __restrict__ b_hh,
            int w) {
    const int l  = blockIdx.x >> 5;
    const int cb = blockIdx.x & 31;
    const int t  = w - l;
    if (t < 0 || t >= TT) return;

    __shared__ float red[8][32][32];

    const int rs = (w + 1) & 1;
    const int ws = w & 1;

    const uint4* inp_pack = (l == 0) ? &g_xpack16[t][0][0][0]
                                     : &g_apack16[rs][l - 1][0][0][0];
    const uint4* h_pack = &g_apack16[rs][l][0][0][0];
    const float* hprev  = &g_ring[rs][l][0][0];
    float*       hout   = &g_ring[ws][l][0][0];

    const int lane = threadIdx.x & 31;
    const int warp = threadIdx.x >> 5;
    const int mstrip = warp & 3;
    const int ksplit = (warp >> 2) & 1;
    const int jhalf  = warp >> 3;
    const int gid = lane >> 2;
    const int tig = lane & 3;
    const int c0 = cb * 32;

    const int bpair = mstrip * 8 + gid;
    const int pidx  = cb * 16 + jhalf * 8 + gid;
    const int kc_lo = ksplit * 32;

    // ---- hoisted epilogue operands (issued now, consumed after k-loop) ----
    const int jtl   = ksplit;                        // this warp's epilogue jt-tile
    const int jbase = (jhalf * 2 + jtl) * 8 + tig * 2;
    const int cA = c0 + jbase;                       // column pair {cA, cA+1}
    const float* bi = b_ih + l * 3 * HID;
    const float* bh = b_hh + l * 3 * HID;
    float bpr[2], bpz[2], bgn[2], bhn[2];
#pragma unroll
    for (int par = 0; par < 2; ++par) {
        const int c = cA + par;
        bpr[par] = bi[c] + bh[c];
        bpz[par] = bi[HID + c] + bh[HID + c];
        bgn[par] = bi[2 * HID + c];
        bhn[par] = bh[2 * HID + c];
    }
    float hp[2][2];
#pragma unroll
    for (int half = 0; half < 2; ++half) {
        const int b = mstrip * 16 + gid + half * 8;
#pragma unroll
        for (int par = 0; par < 2; ++par)
            hp[half][par] = hprev[(int64_t)b * HID + cA + par];
    }

    // acc[group][jtl][reg]; groups: 0=r, 1=z, 2=gi_n, 3=gh_n
    float acc[4][2][4];
#pragma unroll
    for (int g = 0; g < 4; ++g)
#pragma unroll
        for (int j = 0; j < 2; ++j)
#pragma unroll
            for (int r = 0; r < 4; ++r) acc[g][j][r] = 0.f;

    // ---- k-loop: EXACT R6 champion body (plain indexed loads, unroll 4) ----
#pragma unroll
    for (int phase = 0; phase < 2; ++phase) {
        const uint4* apack = phase ? h_pack : inp_pack;
        const uint4* pa = apack + (((int64_t)bpair * 64 + kc_lo) << 2) + tig;
        const uint4* pb = g_wpack16
            + ((((int64_t)(l * 2 + phase) * 64 + kc_lo) * 3) * 512 + pidx) * 4 + tig;
        const int g_third = phase ? 3 : 2;

#pragma unroll 4
        for (int kk = 0; kk < 32; ++kk) {
            uint4 qa = pa[kk << 2];
            uint32_t Ah[4] = {qa.x, qa.y, qa.z, qa.w};

            const uint4* pbk = pb + (int64_t)kk * (3 * 512 * 4);
            uint4 qb0 = pbk[0];
            uint4 qb1 = pbk[512 * 4];
            uint4 qb2 = pbk[2 * 512 * 4];

            mma_fp16(acc[0][0],       Ah, qb0.x, qb0.y);
            mma_fp16(acc[0][1],       Ah, qb0.z, qb0.w);
            mma_fp16(acc[1][0],       Ah, qb1.x, qb1.y);
            mma_fp16(acc[1][1],       Ah, qb1.z, qb1.w);
            mma_fp16(acc[g_third][0], Ah, qb2.x, qb2.y);
            mma_fp16(acc[g_third][1], Ah, qb2.z, qb2.w);
        }
    }

    // ---- cross-warp K reduction: each warp exports its "other" jtl ----
    {
        const int je = 1 - ksplit;
        float* dst = &red[jhalf * 4 + mstrip][lane][je * 16];
#pragma unroll
        for (int g = 0; g < 4; ++g)
#pragma unroll
            for (int r = 0; r < 4; ++r) dst[g * 4 + r] = acc[g][je][r];
    }
    __syncthreads();

    // ---- gates for jtl = ksplit (all warps work) ----
    {
        const float* srcr = &red[jhalf * 4 + mstrip][lane][jtl * 16];
#pragma unroll
        for (int g = 0; g < 4; ++g)
#pragma unroll
            for (int r = 0; r < 4; ++r) acc[g][jtl][r] += srcr[g * 4 + r];

        uint32_t frag[2];
#pragma unroll
        for (int half = 0; half < 2; ++half) {
            const int b = mstrip * 16 + gid + half * 8;
            float hnew[2];
#pragma unroll
            for (int par = 0; par < 2; ++par) {
                const int c = cA + par;
                const int ri = half * 2 + par;
                float pr  = acc[0][jtl][ri] + bpr[par];
                float pz  = acc[1][jtl][ri] + bpz[par];
                float gin = acc[2][jtl][ri] + bgn[par];
                float ghn = acc[3][jtl][ri] + bhn[par];
                float rr = 1.f / (1.f + __expf(-pr));
                float zz = 1.f / (1.f + __expf(-pz));
                float nn = tanhf(gin + rr * ghn);
                hnew[par] = (1.f - zz) * nn + zz * hp[half][par];
                hout[(int64_t)b * HID + c] = hnew[par];
            }
            frag[half] = f2h2(hnew[0], hnew[1]);
        }
        // apack uint4 = {jtl0h0, jtl0h1, jtl1h0, jtl1h1}; this warp owns words [jtl*2, jtl*2+1]
        uint2 q2; q2.x = frag[0]; q2.y = frag[1];
        char* base = (char*)&g_apack16[ws][l][bpair][cb * 2 + jhalf][tig];
        *reinterpret_cast<uint2*>(base + jtl * 8) = q2;
    }
}

// ---------- output copy ----------
__global__ void copy_out_kernel(float* __restrict__ out) {
    int idx = blockIdx.x * blockDim.x + threadIdx.x;   // < L*B*H
    int l = idx >> 16;
    int rest = idx & 0xFFFF;
    int slot = (TT - 1 + l) & 1;
    out[idx] = (&g_ring[slot][l][0][0])[rest];
}

// ---------- launch ----------
extern "C" void kernel_launch(void* const* d_in, const int* in_sizes, int n_in,
                              void* d_out, int out_size) {
    const float* x    = (const float*)d_in[0];
    const float* h0   = (const float*)d_in[1];
    const float* w_ih = (const float*)d_in[2];
    const float* w_hh = (const float*)d_in[3];
    const float* b_ih = (const float*)d_in[4];
    const float* b_hh = (const float*)d_in[5];
    float* out = (float*)d_out;

    {
        int64_t total = 8ll * 64 * 3 * 512 * 4;
        pack_weights16_kernel<<<(int)((total + 255) / 256), 256>>>(w_ih, w_hh);
    }
    {
        int64_t total = (int64_t)TT * 32 * 64 * 4;
        pack_x16_kernel<<<(int)((total + 255) / 256), 256>>>(x);
    }
    init_h0_kernel<<<(LAY * 32 * 64 * 4) / 256, 256>>>(h0);

    for (int w = 0; w < NWAVE; ++w) {
        wave_kernel<<<128, 512>>>(b_ih, b_hh, w);
    }

    copy_out_kernel<<<(LAY * BB * HID) / 256, 256>>>(out);
}